// round 12
// baseline (speedup 1.0000x reference)
#include <cuda_runtime.h>
#include <cuda_bf16.h>
#include <math.h>

#define NM      4096
#define NPTS    131072
#define GRES    16

typedef unsigned int u32;

// ---- scratch (no allocations allowed) ----
__device__ int g_cnt[NM];      // zero at load; re-zeroed by k_mlp each call
__device__ int g_off[NM];
__device__ int g_start[NM];
__device__ int g_vox[NPTS];
__device__ int g_sorted[NPTS];

__global__ void k_index(const float* __restrict__ pts) {
    int n = blockIdx.x * blockDim.x + threadIdx.x;
    if (n >= NPTS) return;
    float x = pts[3 * n + 0], y = pts[3 * n + 1], z = pts[3 * n + 2];
    int ix = (int)fminf(fmaxf(x * (float)GRES, 0.f), (float)(GRES - 1));
    int iy = (int)fminf(fmaxf(y * (float)GRES, 0.f), (float)(GRES - 1));
    int iz = (int)fminf(fmaxf(z * (float)GRES, 0.f), (float)(GRES - 1));
    int v = ix * (GRES * GRES) + iy * GRES + iz;
    g_vox[n] = v;
    atomicAdd(&g_cnt[v], 1);
}

__global__ void k_scan() {
    __shared__ int sh[1024];
    int t = threadIdx.x;
    int c0 = g_cnt[4 * t + 0], c1 = g_cnt[4 * t + 1];
    int c2 = g_cnt[4 * t + 2], c3 = g_cnt[4 * t + 3];
    int s = c0 + c1 + c2 + c3;
    sh[t] = s;
    __syncthreads();
    for (int d = 1; d < 1024; d <<= 1) {
        int v = (t >= d) ? sh[t - d] : 0;
        __syncthreads();
        sh[t] += v;
        __syncthreads();
    }
    int excl = sh[t] - s;
    g_start[4 * t + 0] = excl; g_off[4 * t + 0] = excl; excl += c0;
    g_start[4 * t + 1] = excl; g_off[4 * t + 1] = excl; excl += c1;
    g_start[4 * t + 2] = excl; g_off[4 * t + 2] = excl; excl += c2;
    g_start[4 * t + 3] = excl; g_off[4 * t + 3] = excl;
}

__global__ void k_scatter() {
    int n = blockIdx.x * blockDim.x + threadIdx.x;
    if (n >= NPTS) return;
    int v = g_vox[n];
    int pos = atomicAdd(&g_off[v], 1);
    g_sorted[pos] = n;
}

// ---- bf16 split helpers ----
// pack x as (x2<<16)|x1 where x = x1 + x2 (both bf16), x1 = rn(x)
__device__ __forceinline__ u32 pack_split(float f) {
    __nv_bfloat16 h1 = __float2bfloat16(f);
    float f1 = __bfloat162float(h1);
    __nv_bfloat16 h2 = __float2bfloat16(f - f1);
    u32 lo = (u32)__bfloat16_as_ushort(h1);
    u32 hi = (u32)__bfloat16_as_ushort(h2);
    return lo | (hi << 16);
}

// mma.sync m16n8k16 row.col f32 += bf16*bf16
__device__ __forceinline__ void mma4(float* C, const u32* a, u32 b0, u32 b1) {
    asm volatile(
        "mma.sync.aligned.m16n8k16.row.col.f32.bf16.bf16.f32 "
        "{%0,%1,%2,%3}, {%4,%5,%6,%7}, {%8,%9}, {%0,%1,%2,%3};"
        : "+f"(C[0]), "+f"(C[1]), "+f"(C[2]), "+f"(C[3])
        : "r"(a[0]), "r"(a[1]), "r"(a[2]), "r"(a[3]), "r"(b0), "r"(b1));
}

// ---- weight staging: (32 outputs x DREAL) fp32 row-major ->
//      B fragments, K'-interleaved (w1,w2) packed, padded to DPAD ----
template<int DREAL, int DPAD>
__device__ __forceinline__ void stage_wf(const float* __restrict__ gsrc,
                                         u32* Wf, int tileOff, int tid) {
    const int total = 32 * DPAD;
    for (int i = tid; i < total; i += 64) {
        int no = i / DPAD;          // output neuron 0..31
        int d  = i % DPAD;          // input dim
        float w = (d < DREAL) ? gsrc[no * DREAL + d] : 0.f;
        u32 pk = pack_split(w);     // low = w1, high = w2  (K slots 2d, 2d+1)
        int kt = d >> 3;
        int dl = d & 7;
        int rg = dl >> 2;           // b0 or b1
        int tc = dl & 3;
        int lane = ((no & 7) << 2) | tc;
        int nt = no >> 3;
        Wf[(((tileOff + kt * 4 + nt) << 5) + lane) * 2 + rg] = pk;
    }
}

// ---- one GEMM layer: C[2][4][4] = X(32 x K'=16*KT) @ B + bias ----
// Xb: warp's Xbuf base (u32, stride 68 per row, packed (x1,x2))
template<int KT>
__device__ __forceinline__ void run_layer(const u32* __restrict__ Wt,
                                          const u32* __restrict__ Xb,
                                          const float* __restrict__ bias,
                                          float C[2][4][4], int g, int tc, int lane) {
#pragma unroll
    for (int nt = 0; nt < 4; nt++) {
        float b0 = bias[nt * 8 + 2 * tc], b1 = bias[nt * 8 + 2 * tc + 1];
#pragma unroll
        for (int mt = 0; mt < 2; mt++) {
            C[mt][nt][0] = b0; C[mt][nt][1] = b1;
            C[mt][nt][2] = b0; C[mt][nt][3] = b1;
        }
    }
#pragma unroll
    for (int kt = 0; kt < KT; kt++) {
        int dA = 8 * kt + tc;
        u32 p1[2][4], p2[2][4];
#pragma unroll
        for (int mt = 0; mt < 2; mt++) {
            int r0 = 16 * mt + g;
            u32 v0 = Xb[r0 * 68 + dA];
            u32 v1 = Xb[(r0 + 8) * 68 + dA];
            u32 v2 = Xb[r0 * 68 + dA + 4];
            u32 v3 = Xb[(r0 + 8) * 68 + dA + 4];
            p1[mt][0] = __byte_perm(v0, 0, 0x1010); p2[mt][0] = __byte_perm(v0, 0, 0x5432);
            p1[mt][1] = __byte_perm(v1, 0, 0x1010); p2[mt][1] = __byte_perm(v1, 0, 0x5432);
            p1[mt][2] = __byte_perm(v2, 0, 0x1010); p2[mt][2] = __byte_perm(v2, 0, 0x5432);
            p1[mt][3] = __byte_perm(v3, 0, 0x1010); p2[mt][3] = __byte_perm(v3, 0, 0x5432);
        }
        const u32* wrow = Wt + ((kt * 4) << 6) + lane * 2;
#pragma unroll
        for (int nt = 0; nt < 4; nt++) {
            u32 b0 = wrow[0], b1 = wrow[1];
            wrow += 64;
            mma4(C[0][nt], p1[0], b0, b1);   // pass1: x1*(w1+w2)
            mma4(C[0][nt], p2[0], b0, b1);   // pass2: x2*w1
            mma4(C[1][nt], p1[1], b0, b1);
            mma4(C[1][nt], p2[1], b0, b1);
        }
    }
}

__device__ __forceinline__ void relu_C(float C[2][4][4]) {
#pragma unroll
    for (int mt = 0; mt < 2; mt++)
#pragma unroll
        for (int nt = 0; nt < 4; nt++)
#pragma unroll
            for (int r = 0; r < 4; r++)
                C[mt][nt][r] = fmaxf(C[mt][nt][r], 0.f);
}

// write C back to Xbuf as packed bf16 splits (cols 0..31)
__device__ __forceinline__ void store_packed(u32* Xb, const float C[2][4][4],
                                             int g, int tc) {
#pragma unroll
    for (int mt = 0; mt < 2; mt++) {
        int r0 = 16 * mt + g;
#pragma unroll
        for (int nt = 0; nt < 4; nt++) {
            int c0 = nt * 8 + 2 * tc;
            Xb[r0 * 68 + c0]           = pack_split(C[mt][nt][0]);
            Xb[r0 * 68 + c0 + 1]       = pack_split(C[mt][nt][1]);
            Xb[(r0 + 8) * 68 + c0]     = pack_split(C[mt][nt][2]);
            Xb[(r0 + 8) * 68 + c0 + 1] = pack_split(C[mt][nt][3]);
        }
    }
}

// write C back as fp32 (final layer output for rgb epilogue)
__device__ __forceinline__ void store_f32(float* Xf, const float C[2][4][4],
                                          int g, int tc) {
#pragma unroll
    for (int mt = 0; mt < 2; mt++) {
        int r0 = 16 * mt + g;
#pragma unroll
        for (int nt = 0; nt < 4; nt++) {
            int c0 = nt * 8 + 2 * tc;
            Xf[r0 * 68 + c0]           = C[mt][nt][0];
            Xf[r0 * 68 + c0 + 1]       = C[mt][nt][1];
            Xf[(r0 + 8) * 68 + c0]     = C[mt][nt][2];
            Xf[(r0 + 8) * 68 + c0 + 1] = C[mt][nt][3];
        }
    }
}

__device__ __forceinline__ void embed_xyz(u32* row, float px, float py, float pz) {
    row[0] = pack_split(px); row[1] = pack_split(py); row[2] = pack_split(pz);
    float sx = __sinf(px), cx = __cosf(px);
    float sy = __sinf(py), cy = __cosf(py);
    float sz = __sinf(pz), cz = __cosf(pz);
#pragma unroll
    for (int k = 0; k < 10; k++) {
        int b = 3 + 6 * k;
        row[b + 0] = pack_split(sx); row[b + 1] = pack_split(sy);
        row[b + 2] = pack_split(sz); row[b + 3] = pack_split(cx);
        row[b + 4] = pack_split(cy); row[b + 5] = pack_split(cz);
        float t;
        t = 2.f * sx * cx; cx = 1.f - 2.f * sx * sx; sx = t;
        t = 2.f * sy * cy; cy = 1.f - 2.f * sy * sy; sy = t;
        t = 2.f * sz * cz; cz = 1.f - 2.f * sz * sz; sz = t;
    }
    row[63] = 0;
}

__device__ __forceinline__ void embed_dir(u32* row, float dx, float dy, float dz) {
    row[32] = pack_split(dx); row[33] = pack_split(dy); row[34] = pack_split(dz);
    float sx = __sinf(dx), cx = __cosf(dx);
    float sy = __sinf(dy), cy = __cosf(dy);
    float sz = __sinf(dz), cz = __cosf(dz);
#pragma unroll
    for (int k = 0; k < 4; k++) {
        int b = 35 + 6 * k;
        row[b + 0] = pack_split(sx); row[b + 1] = pack_split(sy);
        row[b + 2] = pack_split(sz); row[b + 3] = pack_split(cx);
        row[b + 4] = pack_split(cy); row[b + 5] = pack_split(cz);
        float t;
        t = 2.f * sx * cx; cx = 1.f - 2.f * sx * sx; sx = t;
        t = 2.f * sy * cy; cy = 1.f - 2.f * sy * sy; sy = t;
        t = 2.f * sz * cz; cz = 1.f - 2.f * sz * sz; sz = t;
    }
#pragma unroll
    for (int c = 59; c < 64; c++) row[c] = 0;
}

// smem layout (u32): Wf[6144] | Xbuf[64*68=4352] | small[324 floats]
#define OFF_XBUF 6144
#define OFF_SM   10496
#define SP_TOT   10820
// small floats: sw[0:32) b0[32:64) b1[64:96) fb[96:128) vb[128:160)
//               rT[160:256) rb[256:259) sb[259] stash[260:324)

__global__ void __launch_bounds__(64, 5) k_mlp(
    const float* __restrict__ pts, const float* __restrict__ vdirs,
    const float* __restrict__ w0, const float* __restrict__ b0,
    const float* __restrict__ w1, const float* __restrict__ b1,
    const float* __restrict__ fw, const float* __restrict__ fb,
    const float* __restrict__ sw, const float* __restrict__ sb,
    const float* __restrict__ vw, const float* __restrict__ vb,
    const float* __restrict__ rw, const float* __restrict__ rb,
    float* __restrict__ out)
{
    const int vox = blockIdx.x;
    const int tid = threadIdx.x;

    __shared__ __align__(16) u32 spool[SP_TOT];
    u32* Wf = spool;
    float* sm = (float*)(spool + OFF_SM);
    float* stash = sm + 260;

    const int start = g_start[vox];
    const int count = g_cnt[vox];

    // stage weights into B-fragment layout (tile offsets in 64-u32 tiles)
    stage_wf<63, 64>(w0 + (size_t)vox * 2016, Wf, 0,  tid);  // 32 tiles
    stage_wf<32, 32>(w1 + (size_t)vox * 1024, Wf, 32, tid);  // 16 tiles
    stage_wf<32, 32>(fw + (size_t)vox * 1024, Wf, 48, tid);  // 16 tiles
    stage_wf<59, 64>(vw + (size_t)vox * 1888, Wf, 64, tid);  // 32 tiles

    for (int i = tid; i < 96; i += 64) {
        int c = i >> 5, d = i & 31;
        sm[160 + d * 3 + c] = rw[(size_t)vox * 96 + i];
    }
    if (tid < 32) {
        sm[tid]       = sw[(size_t)vox * 32 + tid];
        sm[32 + tid]  = b0[(size_t)vox * 32 + tid];
        sm[64 + tid]  = b1[(size_t)vox * 32 + tid];
        sm[96 + tid]  = fb[(size_t)vox * 32 + tid];
        sm[128 + tid] = vb[(size_t)vox * 32 + tid];
    }
    if (tid < 3) sm[256 + tid] = rb[(size_t)vox * 3 + tid];
    if (tid == 0) {
        sm[259] = sb[vox];
        g_cnt[vox] = 0;   // reset for next replay
    }
    __syncthreads();

    const int warp = tid >> 5, lane = tid & 31;
    const int g = lane >> 2, tc = lane & 3;
    u32* Xb = spool + OFF_XBUF + warp * (32 * 68);

    // warps alternate full 32-point chunks
    for (int base = warp * 32; base < count; base += 64) {
        const int i = base + lane;
        const bool act = (i < count);
        int n = 0;
        float px = 0.f, py = 0.f, pz = 0.f, dvx = 0.f, dvy = 0.f, dvz = 0.f;
        if (act) {
            n = g_sorted[start + i];
            px = pts[3 * n + 0]; py = pts[3 * n + 1]; pz = pts[3 * n + 2];
            int ray = n >> 7;   // N_SAMPLES = 128
            dvx = vdirs[3 * ray + 0]; dvy = vdirs[3 * ray + 1]; dvz = vdirs[3 * ray + 2];
        }

        // layer0 input: embed into Xbuf (row = lane)
        embed_xyz(Xb + lane * 68, px, py, pz);
        __syncwarp();

        float C[2][4][4];

        // ---- layer0: 63->32, relu ----
        run_layer<8>(Wf + 0 * 64, Xb, sm + 32, C, g, tc, lane);
        relu_C(C);
        __syncwarp();
        store_packed(Xb, C, g, tc);
        __syncwarp();

        // ---- layer1: 32->32, relu ----
        run_layer<4>(Wf + 32 * 64, Xb, sm + 64, C, g, tc, lane);
        relu_C(C);

        // ---- sigma from h (C regs), butterfly over tc ----
        {
            float s0 = 0.f, s1 = 0.f, s2 = 0.f, s3 = 0.f;
#pragma unroll
            for (int nt = 0; nt < 4; nt++) {
                float wv0 = sm[nt * 8 + 2 * tc], wv1 = sm[nt * 8 + 2 * tc + 1];
                s0 += C[0][nt][0] * wv0 + C[0][nt][1] * wv1;
                s1 += C[0][nt][2] * wv0 + C[0][nt][3] * wv1;
                s2 += C[1][nt][0] * wv0 + C[1][nt][1] * wv1;
                s3 += C[1][nt][2] * wv0 + C[1][nt][3] * wv1;
            }
            s0 += __shfl_xor_sync(0xFFFFFFFFu, s0, 1);
            s0 += __shfl_xor_sync(0xFFFFFFFFu, s0, 2);
            s1 += __shfl_xor_sync(0xFFFFFFFFu, s1, 1);
            s1 += __shfl_xor_sync(0xFFFFFFFFu, s1, 2);
            s2 += __shfl_xor_sync(0xFFFFFFFFu, s2, 1);
            s2 += __shfl_xor_sync(0xFFFFFFFFu, s2, 2);
            s3 += __shfl_xor_sync(0xFFFFFFFFu, s3, 1);
            s3 += __shfl_xor_sync(0xFFFFFFFFu, s3, 2);
            if (tc == 0) {
                float sbv = sm[259];
                stash[warp * 32 + g]      = s0 + sbv;
                stash[warp * 32 + g + 8]  = s1 + sbv;
                stash[warp * 32 + g + 16] = s2 + sbv;
                stash[warp * 32 + g + 24] = s3 + sbv;
            }
        }
        __syncwarp();
        store_packed(Xb, C, g, tc);
        __syncwarp();

        // ---- feat: 32->32, NO relu ----
        run_layer<4>(Wf + 48 * 64, Xb, sm + 96, C, g, tc, lane);
        __syncwarp();
        store_packed(Xb, C, g, tc);
        // view input cols 32..63: dir embedding (row = lane)
        embed_dir(Xb + lane * 68, dvx, dvy, dvz);
        __syncwarp();

        // ---- view: 59->32, relu ----
        run_layer<8>(Wf + 64 * 64, Xb, sm + 128, C, g, tc, lane);
        relu_C(C);
        __syncwarp();
        store_f32((float*)Xb, C, g, tc);
        __syncwarp();

        // ---- epilogue: rgb (3) + sigma, lane = point row ----
        if (act) {
            const float* xr = (const float*)Xb + lane * 68;
            float r0 = sm[256], r1 = sm[257], r2 = sm[258];
#pragma unroll
            for (int d = 0; d < 32; d++) {
                float h = xr[d];
                r0 = fmaf(h, sm[160 + d * 3 + 0], r0);
                r1 = fmaf(h, sm[160 + d * 3 + 1], r1);
                r2 = fmaf(h, sm[160 + d * 3 + 2], r2);
            }
            out[3 * n + 0] = r0;
            out[3 * n + 1] = r1;
            out[3 * n + 2] = r2;
            out[(size_t)NPTS * 3 + n] = stash[warp * 32 + lane];
        }
        __syncwarp();
    }
}

extern "C" void kernel_launch(void* const* d_in, const int* in_sizes, int n_in,
                              void* d_out, int out_size) {
    (void)in_sizes; (void)n_in; (void)out_size;
    const float* pts = (const float*)d_in[0];
    const float* vd  = (const float*)d_in[1];
    const float* w0  = (const float*)d_in[2];
    const float* b0  = (const float*)d_in[3];
    const float* w1  = (const float*)d_in[4];
    const float* b1  = (const float*)d_in[5];
    const float* fw  = (const float*)d_in[6];
    const float* fb  = (const float*)d_in[7];
    const float* sw  = (const float*)d_in[8];
    const float* sb  = (const float*)d_in[9];
    const float* vw  = (const float*)d_in[10];
    const float* vb  = (const float*)d_in[11];
    const float* rw  = (const float*)d_in[12];
    const float* rb  = (const float*)d_in[13];

    k_index<<<512, 256>>>(pts);
    k_scan<<<1, 1024>>>();
    k_scatter<<<512, 256>>>();
    k_mlp<<<NM, 64>>>(pts, vd, w0, b0, w1, b1, fw, fb, sw, sb, vw, vb, rw, rb,
                      (float*)d_out);
}

// round 13
// speedup vs baseline: 1.1441x; 1.1441x over previous
#include <cuda_runtime.h>
#include <math.h>

#define NM      4096
#define NPTS    131072
#define GRES    16

typedef unsigned long long u64;

// ---- scratch (no allocations allowed) ----
__device__ int g_cnt[NM];      // zero at load; re-zeroed by k_mlp each call
__device__ int g_start[NM];
__device__ int g_vox[NPTS];    // packed: voxel | (rank<<12)
__device__ int g_sorted[NPTS];

__global__ void k_index(const float* __restrict__ pts) {
    int n = blockIdx.x * blockDim.x + threadIdx.x;
    if (n >= NPTS) return;
    float x = pts[3 * n + 0], y = pts[3 * n + 1], z = pts[3 * n + 2];
    int ix = (int)fminf(fmaxf(x * (float)GRES, 0.f), (float)(GRES - 1));
    int iy = (int)fminf(fmaxf(y * (float)GRES, 0.f), (float)(GRES - 1));
    int iz = (int)fminf(fmaxf(z * (float)GRES, 0.f), (float)(GRES - 1));
    int v = ix * (GRES * GRES) + iy * GRES + iz;
    int r = atomicAdd(&g_cnt[v], 1);      // rank within voxel, computed once
    g_vox[n] = v | (r << 12);
}

// one block, 1024 threads, 4 bins each
__global__ void k_scan() {
    __shared__ int sh[1024];
    int t = threadIdx.x;
    int c0 = g_cnt[4 * t + 0], c1 = g_cnt[4 * t + 1];
    int c2 = g_cnt[4 * t + 2], c3 = g_cnt[4 * t + 3];
    int s = c0 + c1 + c2 + c3;
    sh[t] = s;
    __syncthreads();
    for (int d = 1; d < 1024; d <<= 1) {
        int v = (t >= d) ? sh[t - d] : 0;
        __syncthreads();
        sh[t] += v;
        __syncthreads();
    }
    int excl = sh[t] - s;
    g_start[4 * t + 0] = excl; excl += c0;
    g_start[4 * t + 1] = excl; excl += c1;
    g_start[4 * t + 2] = excl; excl += c2;
    g_start[4 * t + 3] = excl;
}

// atomic-free scatter: position = start[v] + precomputed rank
__global__ void k_scatter() {
    int n = blockIdx.x * blockDim.x + threadIdx.x;
    if (n >= NPTS) return;
    int pv = g_vox[n];
    int v = pv & 4095;
    int r = pv >> 12;
    g_sorted[g_start[v] + r] = n;
}

// ---- packed fp32x2 helpers (FFMA2) ----
__device__ __forceinline__ u64 f2fma(u64 a, u64 b, u64 c) {
    u64 d;
    asm("fma.rn.f32x2 %0, %1, %2, %3;" : "=l"(d) : "l"(a), "l"(b), "l"(c));
    return d;
}
__device__ __forceinline__ u64 pk2(float v) {
    u64 r;
    asm("mov.b64 %0, {%1, %1};" : "=l"(r) : "f"(v));
    return r;
}
__device__ __forceinline__ float2 unpk(u64 p) {
    float2 f;
    asm("mov.b64 {%0, %1}, %2;" : "=f"(f.x), "=f"(f.y) : "l"(p));
    return f;
}
__device__ __forceinline__ void accP(u64* P, const float* wrow, u64 v2) {
    const ulonglong2* w = reinterpret_cast<const ulonglong2*>(wrow);
#pragma unroll
    for (int j = 0; j < 8; j++) {
        ulonglong2 ww = w[j];
        P[2 * j + 0] = f2fma(v2, ww.x, P[2 * j + 0]);
        P[2 * j + 1] = f2fma(v2, ww.y, P[2 * j + 1]);
    }
}
__device__ __forceinline__ void loadP(u64* P, const float* s) {
    const ulonglong2* b = reinterpret_cast<const ulonglong2*>(s);
#pragma unroll
    for (int j = 0; j < 8; j++) {
        ulonglong2 v = b[j];
        P[2 * j + 0] = v.x;
        P[2 * j + 1] = v.y;
    }
}
__device__ __forceinline__ void unpackRelu(const u64* P, float* H) {
#pragma unroll
    for (int j = 0; j < 16; j++) {
        float2 f = unpk(P[j]);
        H[2 * j + 0] = fmaxf(f.x, 0.f);
        H[2 * j + 1] = fmaxf(f.y, 0.f);
    }
}
__device__ __forceinline__ void unpackPlain(const u64* P, float* H) {
#pragma unroll
    for (int j = 0; j < 16; j++) {
        float2 f = unpk(P[j]);
        H[2 * j + 0] = f.x;
        H[2 * j + 1] = f.y;
    }
}

// ---- staging: (32 x C) row-major -> T[d*32+o] ----
// 16-row halves through a large scratch region (>= 16*C floats)
__device__ __forceinline__ void stage_odd16(const float* g, float* T, float* tmp,
                                            int tid, int C) {
    for (int h = 0; h < 2; h++) {
        const float4* g4 = reinterpret_cast<const float4*>(g + h * 16 * C);
        float4* t4 = reinterpret_cast<float4*>(tmp);
        int n4 = (16 * C) >> 2;
        for (int i = tid; i < n4; i += 64) t4[i] = g4[i];
        __syncthreads();
        for (int i = tid; i < 16 * C; i += 64) {
            int d = i >> 4, o = i & 15;
            T[d * 32 + h * 16 + o] = tmp[o * C + d];
        }
        __syncthreads();
    }
}
// 32x32, 16-row halves, padded rows (33) in scratch (needs >= 528 floats)
__device__ __forceinline__ void stage32_16(const float* g, float* T, float* tmp,
                                           int tid) {
    for (int h = 0; h < 2; h++) {
        const float* gh = g + h * 512;
        for (int i = tid; i < 512; i += 64)
            tmp[(i >> 5) * 33 + (i & 31)] = gh[i];
        __syncthreads();
        for (int i = tid; i < 512; i += 64) {
            int d = i >> 4, o = i & 15;
            T[d * 32 + h * 16 + o] = tmp[o * 33 + d];
        }
        __syncthreads();
    }
}
// 8-row chunks through small tmp (needs >= 8*C = 504 floats), for w0 staged last
__device__ __forceinline__ void stage_odd8(const float* g, float* T, float* tmp,
                                           int tid, int C) {
#pragma unroll
    for (int h = 0; h < 4; h++) {
        const float4* g4 = reinterpret_cast<const float4*>(g + h * 8 * C);
        float4* t4 = reinterpret_cast<float4*>(tmp);
        int n4 = (8 * C) >> 2;
        for (int i = tid; i < n4; i += 64) t4[i] = g4[i];
        __syncthreads();
        for (int i = tid; i < 8 * C; i += 64) {
            int d = i >> 3, o = i & 7;
            T[d * 32 + h * 8 + o] = tmp[o * C + d];
        }
        __syncthreads();
    }
}

// smem pool layout (floats)
#define OFF_W0T 0        // 2016
#define OFF_W1T 2016     // 1024
#define OFF_FT  3040     // 1024
#define OFF_VT  4064     // 1888
#define OFF_SM  5952     // 264
#define OFF_TMP 6216     // 504 (w0 staging only)
#define SP_TOT  6720     // 26880 bytes

__global__ void __launch_bounds__(64, 7) k_mlp(
    const float* __restrict__ pts, const float* __restrict__ vdirs,
    const float* __restrict__ w0, const float* __restrict__ b0,
    const float* __restrict__ w1, const float* __restrict__ b1,
    const float* __restrict__ fw, const float* __restrict__ fb,
    const float* __restrict__ sw, const float* __restrict__ sb,
    const float* __restrict__ vw, const float* __restrict__ vb,
    const float* __restrict__ rw, const float* __restrict__ rb,
    float* __restrict__ out)
{
    const int vox = blockIdx.x;
    const int tid = threadIdx.x;

    __shared__ __align__(16) float sp[SP_TOT];
    float* s_w0T = sp + OFF_W0T;   // [d=63][o=32]
    float* s_w1T = sp + OFF_W1T;   // [d=32][o=32]
    float* s_fT  = sp + OFF_FT;    // [d=32][o=32]
    float* s_vT  = sp + OFF_VT;    // [d=59][o=32]
    float* s_sm  = sp + OFF_SM;
    float* s_tmp = sp + OFF_TMP;

    const int start = g_start[vox];
    const int count = g_cnt[vox];

    // stage vT/w1T/fT first, borrowing the (still empty) w0T region as scratch;
    // stage w0T last through the small dedicated tmp
    stage_odd16(vw + (size_t)vox * 1888, s_vT, s_w0T, tid, 59);
    stage32_16(w1 + (size_t)vox * 1024, s_w1T, s_w0T, tid);
    stage32_16(fw + (size_t)vox * 1024, s_fT, s_w0T, tid);
    stage_odd8(w0 + (size_t)vox * 2016, s_w0T, s_tmp, tid, 63);

    for (int i = tid; i < 96; i += 64) {
        int c = i >> 5, d = i & 31;
        s_sm[160 + d * 3 + c] = rw[(size_t)vox * 96 + i];
    }
    if (tid < 32) {
        s_sm[tid]       = sw[(size_t)vox * 32 + tid];
        s_sm[32 + tid]  = b0[(size_t)vox * 32 + tid];
        s_sm[64 + tid]  = b1[(size_t)vox * 32 + tid];
        s_sm[96 + tid]  = fb[(size_t)vox * 32 + tid];
        s_sm[128 + tid] = vb[(size_t)vox * 32 + tid];
    }
    if (tid < 3) s_sm[256 + tid] = rb[(size_t)vox * 3 + tid];
    if (tid == 0) {
        s_sm[259] = sb[vox];
        g_cnt[vox] = 0;   // reset for next replay (count already read above)
    }
    __syncthreads();

    const int warp = tid >> 5, lane = tid & 31;

    // full 32-point tiles, warps alternate tiles
    for (int base = warp * 32; base < count; base += 64) {
        const int i = base + lane;
        const bool act = (i < count);
        int n = 0;
        float px = 0.f, py = 0.f, pz = 0.f, dvx = 0.f, dvy = 0.f, dvz = 0.f;
        if (act) {
            n = g_sorted[start + i];
            px = pts[3 * n + 0]; py = pts[3 * n + 1]; pz = pts[3 * n + 2];
            int ray = n >> 7;   // N_SAMPLES = 128
            dvx = vdirs[3 * ray + 0]; dvy = vdirs[3 * ray + 1]; dvz = vdirs[3 * ray + 2];
        }

        u64 P[16];
        float A[32];   // single activation array reused across all layers

        // ---- layer0: 63 -> 32, relu ----
        loadP(P, s_sm + 32);
        accP(P, s_w0T + 0 * 32, pk2(px));
        accP(P, s_w0T + 1 * 32, pk2(py));
        accP(P, s_w0T + 2 * 32, pk2(pz));
        {
            float sx = __sinf(px), cx = __cosf(px);
            float sy = __sinf(py), cy = __cosf(py);
            float sz = __sinf(pz), cz = __cosf(pz);
#pragma unroll
            for (int k = 0; k < 10; k++) {
                const float* r = s_w0T + (3 + 6 * k) * 32;
                accP(P, r + 0 * 32, pk2(sx));
                accP(P, r + 1 * 32, pk2(sy));
                accP(P, r + 2 * 32, pk2(sz));
                accP(P, r + 3 * 32, pk2(cx));
                accP(P, r + 4 * 32, pk2(cy));
                accP(P, r + 5 * 32, pk2(cz));
                float t;
                t = 2.f * sx * cx; cx = 1.f - 2.f * sx * sx; sx = t;
                t = 2.f * sy * cy; cy = 1.f - 2.f * sy * sy; sy = t;
                t = 2.f * sz * cz; cz = 1.f - 2.f * sz * sz; sz = t;
            }
        }
        unpackRelu(P, A);

        // ---- layer1: 32 -> 32, relu (reads all A, then overwrites A) ----
        loadP(P, s_sm + 64);
#pragma unroll
        for (int d = 0; d < 32; d++) accP(P, s_w1T + d * 32, pk2(A[d]));
        unpackRelu(P, A);          // A = h

        // ---- sigma: 32 -> 1 (from h) ----
        float sg = s_sm[259];
#pragma unroll
        for (int d = 0; d < 32; d++) sg = fmaf(A[d], s_sm[d], sg);

        // ---- feat: 32 -> 32 (no relu) ----
        loadP(P, s_sm + 96);
#pragma unroll
        for (int d = 0; d < 32; d++) accP(P, s_fT + d * 32, pk2(A[d]));
        unpackPlain(P, A);         // A = feat

        // ---- view layer: concat(feat[32], ev[27]) -> 32, relu ----
        loadP(P, s_sm + 128);
#pragma unroll
        for (int d = 0; d < 32; d++) accP(P, s_vT + d * 32, pk2(A[d]));
        accP(P, s_vT + 32 * 32, pk2(dvx));
        accP(P, s_vT + 33 * 32, pk2(dvy));
        accP(P, s_vT + 34 * 32, pk2(dvz));
        {
            float sx = __sinf(dvx), cx = __cosf(dvx);
            float sy = __sinf(dvy), cy = __cosf(dvy);
            float sz = __sinf(dvz), cz = __cosf(dvz);
#pragma unroll
            for (int k = 0; k < 4; k++) {
                const float* r = s_vT + (35 + 6 * k) * 32;
                accP(P, r + 0 * 32, pk2(sx));
                accP(P, r + 1 * 32, pk2(sy));
                accP(P, r + 2 * 32, pk2(sz));
                accP(P, r + 3 * 32, pk2(cx));
                accP(P, r + 4 * 32, pk2(cy));
                accP(P, r + 5 * 32, pk2(cz));
                float t;
                t = 2.f * sx * cx; cx = 1.f - 2.f * sx * sx; sx = t;
                t = 2.f * sy * cy; cy = 1.f - 2.f * sy * sy; sy = t;
                t = 2.f * sz * cz; cz = 1.f - 2.f * sz * sz; sz = t;
            }
        }
        unpackRelu(P, A);          // A = view output

        // ---- rgb: 32 -> 3 ----
        float r0 = s_sm[256], r1 = s_sm[257], r2 = s_sm[258];
#pragma unroll
        for (int d = 0; d < 32; d++) {
            r0 = fmaf(A[d], s_sm[160 + d * 3 + 0], r0);
            r1 = fmaf(A[d], s_sm[160 + d * 3 + 1], r1);
            r2 = fmaf(A[d], s_sm[160 + d * 3 + 2], r2);
        }

        if (act) {
            out[3 * n + 0] = r0;
            out[3 * n + 1] = r1;
            out[3 * n + 2] = r2;
            out[(size_t)NPTS * 3 + n] = sg;
        }
    }
}

extern "C" void kernel_launch(void* const* d_in, const int* in_sizes, int n_in,
                              void* d_out, int out_size) {
    (void)in_sizes; (void)n_in; (void)out_size;
    const float* pts = (const float*)d_in[0];
    const float* vd  = (const float*)d_in[1];
    const float* w0  = (const float*)d_in[2];
    const float* b0  = (const float*)d_in[3];
    const float* w1  = (const float*)d_in[4];
    const float* b1  = (const float*)d_in[5];
    const float* fw  = (const float*)d_in[6];
    const float* fb  = (const float*)d_in[7];
    const float* sw  = (const float*)d_in[8];
    const float* sb  = (const float*)d_in[9];
    const float* vw  = (const float*)d_in[10];
    const float* vb  = (const float*)d_in[11];
    const float* rw  = (const float*)d_in[12];
    const float* rb  = (const float*)d_in[13];

    k_index<<<512, 256>>>(pts);
    k_scan<<<1, 1024>>>();
    k_scatter<<<512, 256>>>();
    k_mlp<<<NM, 64>>>(pts, vd, w0, b0, w1, b1, fw, fb, sw, sb, vw, vb, rw, rb,
                      (float*)d_out);
}